// round 8
// baseline (speedup 1.0000x reference)
#include <cuda_runtime.h>
#include <math.h>

#define Nd    128
#define SLICE (Nd * Nd)          // 16384
#define VOL   (Nd * Nd * Nd)     // 2097152
#define NVOLS 8                  // 2 batches * 4 classes

__device__ double g_S1[NVOLS];
__device__ double g_S2[NVOLS];
__device__ double g_Num[NVOLS];
__device__ double g_Den[NVOLS];
__device__ float  g_Mean[NVOLS];
__device__ float  g_scr[(size_t)NVOLS * VOL];   // 64 MiB scratch (HW-blurred labels)

// Gaussian taps exp(-x^2/(2*25)), x=-4..4 (unnormalized, matches reference)
__constant__ float Gc[9] = {
    0.72614903f, 0.83527021f, 0.92311635f, 0.98019867f, 1.0f,
    0.98019867f, 0.92311635f, 0.83527021f, 0.72614903f
};

__device__ __forceinline__ void blockReduceAtomic(float a, float b, double* dA, double* dB) {
    const int tid  = threadIdx.x + threadIdx.y * blockDim.x;
    const int lane = tid & 31;
    const int wid  = tid >> 5;
    #pragma unroll
    for (int off = 16; off; off >>= 1) {
        a += __shfl_down_sync(0xffffffffu, a, off);
        b += __shfl_down_sync(0xffffffffu, b, off);
    }
    __shared__ float sa[16], sb[16];
    if (lane == 0) { sa[wid] = a; sb[wid] = b; }
    __syncthreads();
    if (tid == 0) {
        const int nw = (blockDim.x * blockDim.y) >> 5;
        double A = 0.0, B = 0.0;
        for (int i = 0; i < nw; ++i) { A += (double)sa[i]; B += (double)sb[i]; }
        atomicAdd(dA, A);
        atomicAdd(dB, B);
    }
}

__global__ void k_init() {
    const int i = threadIdx.x;
    if (i < NVOLS) { g_S1[i] = 0.0; g_S2[i] = 0.0; g_Num[i] = 0.0; g_Den[i] = 0.0; }
}

// ---------------------------------------------------------------------------
// Fused pass 1+2: per (iv, d) slice. Stage the 128x128 label slice in smem
// (64KB dynamic), accumulate S1/S2 while staging (float4 streams), W-blur in
// registers (per-thread 32-run, rolling 9-window), write back, H-blur with a
// float4 rolling window over h, store HW-blurred slice straight to g_scr.
// Eliminates the old pass2's 128 MiB scratch round-trip.
// Grid (NVOLS, Nd), block 512. blockIdx.x = iv fast-varying -> the 4 classes
// of a batch hit the same inputs slice back-to-back -> L2 reuse.
// ---------------------------------------------------------------------------
__global__ void k_pass12(const float* __restrict__ labels, const float* __restrict__ inputs) {
    extern __shared__ float s1[];                 // 128*128 floats = 64KB
    const int iv = blockIdx.x;
    const int d  = blockIdx.y;
    const int t  = threadIdx.x;                   // 0..511
    const size_t vbase = (size_t)iv * VOL + (size_t)d * SLICE;
    const float4* __restrict__ L4 = (const float4*)(labels + vbase);
    const float4* __restrict__ I4 = (const float4*)(inputs + (size_t)(iv >> 2) * VOL
                                                           + (size_t)d * SLICE);
    float4* s4 = (float4*)s1;

    // --- stage + fused S1/S2 accumulation (8 float4 per thread, high MLP) ---
    float sumP = 0.f, sumPI = 0.f;
    #pragma unroll
    for (int k = 0; k < 8; ++k) {
        const int idx = t + k * 512;
        const float4 p = L4[idx];
        const float4 v = I4[idx];
        s4[idx] = p;
        sumP  += (p.x + p.y) + (p.z + p.w);
        sumPI += (p.x * v.x + p.y * v.y) + (p.z * v.z + p.w * v.w);
    }
    __syncthreads();

    // --- W-blur: thread owns a contiguous 32-run of one row, output in regs ---
    const int row = t >> 2;
    const int c0  = (t & 3) * 32;
    const float* rp = s1 + row * Nd;
    float win[9];
    #pragma unroll
    for (int j = 0; j < 8; ++j) {
        const int c = c0 - 4 + j;
        win[j] = (c >= 0) ? rp[c] : 0.f;
    }
    float out[32];
    #pragma unroll
    for (int i = 0; i < 32; ++i) {
        const int c = c0 + i + 4;
        win[8] = (c < Nd) ? rp[c] : 0.f;
        float acc = 0.f;
        #pragma unroll
        for (int j = 0; j < 9; ++j) acc += Gc[j] * win[j];
        out[i] = acc;
        #pragma unroll
        for (int k = 0; k < 8; ++k) win[k] = win[k + 1];
    }
    __syncthreads();
    // write W-blurred run back (float4-aligned: c0 multiple of 32)
    float4* wb = (float4*)(s1 + row * Nd + c0);
    #pragma unroll
    for (int k = 0; k < 8; ++k)
        wb[k] = make_float4(out[4*k], out[4*k+1], out[4*k+2], out[4*k+3]);
    __syncthreads();

    // --- H-blur: float4 rolling window over h, direct coalesced global store ---
    const int w4 = t & 31;                        // float4 column 0..31
    const int hb = (t >> 5) * 8;                  // 8 consecutive h per thread
    const float4 z4 = make_float4(0.f, 0.f, 0.f, 0.f);
    float4 vw[9];
    #pragma unroll
    for (int j = 0; j < 8; ++j) {
        const int r = hb - 4 + j;
        vw[j] = (r >= 0) ? s4[r * 32 + w4] : z4;
    }
    float4* __restrict__ O4 = (float4*)(g_scr + vbase);
    #pragma unroll
    for (int i = 0; i < 8; ++i) {
        const int r = hb + i + 4;
        vw[8] = (r < Nd) ? s4[r * 32 + w4] : z4;
        float4 acc = z4;
        #pragma unroll
        for (int j = 0; j < 9; ++j) {
            acc.x += Gc[j] * vw[j].x;
            acc.y += Gc[j] * vw[j].y;
            acc.z += Gc[j] * vw[j].z;
            acc.w += Gc[j] * vw[j].w;
        }
        O4[(hb + i) * 32 + w4] = acc;
        #pragma unroll
        for (int k = 0; k < 8; ++k) vw[k] = vw[k + 1];
    }

    blockReduceAtomic(sumPI, sumP, &g_S1[iv], &g_S2[iv]);
}

__global__ void k_means() {
    const int i = threadIdx.x;
    if (i < NVOLS)
        g_Mean[i] = (float)(g_S1[i] / (g_S2[i] + 1e-5 * (double)VOL));
}

// ---------------------------------------------------------------------------
// Pass 3 (float4): D-blur via rolling float4 window, fused with weights and
// the num/den reductions (self-adjoint blur):
//   num = sum(blur(p) * p * w), den = sum(blur(p) * w), w = exp(-((in-mean)^2)^2)
// Grid (NVOLS, 32, 2), block (32, 4). 3x LDG.128 per iteration -> high MLP.
// ---------------------------------------------------------------------------
__global__ void k_pass3(const float* __restrict__ labels, const float* __restrict__ inputs) {
    const int iv = blockIdx.x;
    const int h  = blockIdx.y * 4 + threadIdx.y;   // 0..127
    const int d0 = blockIdx.z * 64;                // 0 or 64
    const int w4 = threadIdx.x;                    // 0..31
    const float mean = g_Mean[iv];
    const float4* __restrict__ S4 = (const float4*)(g_scr  + (size_t)iv * VOL);
    const float4* __restrict__ L4 = (const float4*)(labels + (size_t)iv * VOL);
    const float4* __restrict__ I4 = (const float4*)(inputs + (size_t)(iv >> 2) * VOL);
    const int hw = h * 32 + w4;
    const float4 z4 = make_float4(0.f, 0.f, 0.f, 0.f);

    float4 vw[9];
    #pragma unroll
    for (int k = 0; k < 8; ++k) {
        const int dd = d0 - 4 + k;
        vw[k] = (dd >= 0) ? S4[dd * (SLICE/4) + hw] : z4;
    }
    float numA = 0.f, denA = 0.f;
    for (int dd = d0; dd < d0 + 64; ++dd) {
        vw[8] = (dd + 4 < Nd) ? S4[(dd + 4) * (SLICE/4) + hw] : z4;
        float4 bp = z4;
        #pragma unroll
        for (int j = 0; j < 9; ++j) {
            bp.x += Gc[j] * vw[j].x;
            bp.y += Gc[j] * vw[j].y;
            bp.z += Gc[j] * vw[j].z;
            bp.w += Gc[j] * vw[j].w;
        }
        const int idx = dd * (SLICE/4) + hw;
        const float4 p = L4[idx];
        const float4 v = I4[idx];
        {
            float df = v.x - mean; df *= df; const float wg = __expf(-df * df);
            numA += bp.x * p.x * wg; denA += bp.x * wg;
        }
        {
            float df = v.y - mean; df *= df; const float wg = __expf(-df * df);
            numA += bp.y * p.y * wg; denA += bp.y * wg;
        }
        {
            float df = v.z - mean; df *= df; const float wg = __expf(-df * df);
            numA += bp.z * p.z * wg; denA += bp.z * wg;
        }
        {
            float df = v.w - mean; df *= df; const float wg = __expf(-df * df);
            numA += bp.w * p.w * wg; denA += bp.w * wg;
        }
        #pragma unroll
        for (int k = 0; k < 8; ++k) vw[k] = vw[k + 1];
    }
    blockReduceAtomic(numA, denA, &g_Num[iv], &g_Den[iv]);
}

__global__ void k_final(float* __restrict__ out) {
    if (threadIdx.x == 0) {
        double loss = 0.0;
        for (int k = 0; k < 4; ++k) {
            const double nn = g_Num[k] + g_Num[k + 4];
            const double dd = g_Den[k] + g_Den[k + 4];
            loss += fabs(nn / (dd + 1e-6));
        }
        out[0] = (float)(4.0 - loss);
    }
}

extern "C" void kernel_launch(void* const* d_in, const int* in_sizes, int n_in,
                              void* d_out, int out_size) {
    const float* labels = (const float*)d_in[0];
    const float* inputs = (const float*)d_in[1];
    if (n_in >= 2 && in_sizes[0] < in_sizes[1]) {
        labels = (const float*)d_in[1];
        inputs = (const float*)d_in[0];
    }
    static bool attr_set = false;
    if (!attr_set) {
        cudaFuncSetAttribute(k_pass12, cudaFuncAttributeMaxDynamicSharedMemorySize, 65536);
        attr_set = true;
    }
    k_init<<<1, 32>>>();
    k_pass12<<<dim3(NVOLS, Nd), 512, 65536>>>(labels, inputs);
    k_means<<<1, 32>>>();
    k_pass3<<<dim3(NVOLS, 32, 2), dim3(32, 4)>>>(labels, inputs);
    k_final<<<1, 32>>>((float*)d_out);
    (void)out_size;
}

// round 11
// speedup vs baseline: 1.3113x; 1.3113x over previous
#include <cuda_runtime.h>
#include <math.h>

#define Nd    128
#define SLICE (Nd * Nd)          // 16384
#define VOL   (Nd * Nd * Nd)     // 2097152
#define NVOLS 8                  // 2 batches * 4 classes

__device__ double g_S1[NVOLS];
__device__ double g_S2[NVOLS];
__device__ double g_Num[NVOLS];
__device__ double g_Den[NVOLS];
__device__ float  g_Mean[NVOLS];
__device__ float  g_scr[(size_t)NVOLS * VOL];   // 64 MiB scratch

// Gaussian taps exp(-x^2/(2*25)), x=-4..4 (unnormalized, matches reference)
__constant__ float Gc[9] = {
    0.72614903f, 0.83527021f, 0.92311635f, 0.98019867f, 1.0f,
    0.98019867f, 0.92311635f, 0.83527021f, 0.72614903f
};

__device__ __forceinline__ void blockReduceAtomic(float a, float b, double* dA, double* dB) {
    const int tid  = threadIdx.x + threadIdx.y * blockDim.x;
    const int lane = tid & 31;
    const int wid  = tid >> 5;
    #pragma unroll
    for (int off = 16; off; off >>= 1) {
        a += __shfl_down_sync(0xffffffffu, a, off);
        b += __shfl_down_sync(0xffffffffu, b, off);
    }
    __shared__ float sa[16], sb[16];
    if (lane == 0) { sa[wid] = a; sb[wid] = b; }
    __syncthreads();
    if (tid == 0) {
        const int nw = (blockDim.x * blockDim.y) >> 5;
        double A = 0.0, B = 0.0;
        for (int i = 0; i < nw; ++i) { A += (double)sa[i]; B += (double)sb[i]; }
        atomicAdd(dA, A);
        atomicAdd(dB, B);
    }
}

__global__ void k_init() {
    const int i = threadIdx.x;
    if (i < NVOLS) { g_S1[i] = 0.0; g_S2[i] = 0.0; g_Num[i] = 0.0; g_Den[i] = 0.0; }
}

// ---------------------------------------------------------------------------
// Pass 1: W-blur labels -> g_scr, fused with S1 = sum(p*in), S2 = sum(p).
// 16-row tile staged fully before a SINGLE sync: 32 independent LDGs/thread
// (high MLP). Thread-per-column smem reads are bank-conflict free.
// Grid (NVOLS, 1024) iv fast-varying -> 4 classes/batch reuse inputs via L2.
// ---------------------------------------------------------------------------
__global__ void k_pass1(const float* __restrict__ labels, const float* __restrict__ inputs) {
    const int iv = blockIdx.x;
    const int rg = blockIdx.y;            // 16-row group, 0..1023
    const int w  = threadIdx.x;           // 0..127
    __shared__ float s[16][Nd + 8];
    const size_t rbase = (size_t)rg * 16 * Nd;
    const float* Lv = labels + (size_t)iv * VOL + rbase;
    const float* Iv = inputs + (size_t)(iv >> 2) * VOL + rbase;
    float*       Ov = g_scr  + (size_t)iv * VOL + rbase;

    float pv[16], vv[16];
    #pragma unroll
    for (int r = 0; r < 16; ++r) pv[r] = Lv[r * Nd + w];   // 16 independent loads
    #pragma unroll
    for (int r = 0; r < 16; ++r) vv[r] = Iv[r * Nd + w];   // 16 independent loads

    float sumP = 0.f, sumPI = 0.f;
    #pragma unroll
    for (int r = 0; r < 16; ++r) {
        s[r][4 + w] = pv[r];
        sumP  += pv[r];
        sumPI += pv[r] * vv[r];
    }
    if (w < 4) {
        #pragma unroll
        for (int r = 0; r < 16; ++r) { s[r][w] = 0.f; s[r][Nd + 4 + w] = 0.f; }
    }
    __syncthreads();

    #pragma unroll
    for (int r = 0; r < 16; ++r) {
        float acc = 0.f;
        #pragma unroll
        for (int j = 0; j < 9; ++j) acc += Gc[j] * s[r][w + j];
        Ov[r * Nd + w] = acc;
    }
    blockReduceAtomic(sumPI, sumP, &g_S1[iv], &g_S2[iv]);
}

__global__ void k_means() {
    const int i = threadIdx.x;
    if (i < NVOLS)
        g_Mean[i] = (float)(g_S1[i] / (g_S2[i] + 1e-5 * (double)VOL));
}

// ---------------------------------------------------------------------------
// Pass 2: H-blur in-place in g_scr. Rolling 9-tap window; h-loop unrolled x8
// with the next-8 loads hoisted into an independent batch -> MLP ~ 8.
// In-place is safe per-thread: element (h+4) is read before (h) is written.
// ---------------------------------------------------------------------------
__global__ void k_pass2() {
    const int d  = blockIdx.x;            // 0..127
    const int iv = blockIdx.y;            // 0..7
    const int w  = threadIdx.x;           // 0..127
    float* base = g_scr + (size_t)iv * VOL + (size_t)d * SLICE;

    float win[9];
    #pragma unroll
    for (int k = 0; k < 4; ++k) win[k] = 0.f;
    #pragma unroll
    for (int k = 0; k < 4; ++k) win[4 + k] = base[k * Nd + w];

    for (int h0 = 0; h0 < Nd; h0 += 8) {
        float nx[8];
        #pragma unroll
        for (int k = 0; k < 8; ++k) {         // 8 independent loads, batched
            const int hh = h0 + k + 4;
            nx[k] = (hh < Nd) ? base[hh * Nd + w] : 0.f;
        }
        #pragma unroll
        for (int k = 0; k < 8; ++k) {
            win[8] = nx[k];
            float acc = 0.f;
            #pragma unroll
            for (int j = 0; j < 9; ++j) acc += Gc[j] * win[j];
            base[(h0 + k) * Nd + w] = acc;
            #pragma unroll
            for (int m = 0; m < 8; ++m) win[m] = win[m + 1];
        }
    }
}

// ---------------------------------------------------------------------------
// Pass 3: D-blur (rolling window) fused with weights + num/den reductions via
// blur self-adjointness:
//   num = sum(blur(p) * p * w), den = sum(blur(p) * w), w = exp(-((in-mean)^2)^2)
// Scalar, 262K threads (55 warps/SM), d-loop unrolled x4 with 12 loads
// batched per group -> MLP ~ 12.
// ---------------------------------------------------------------------------
__global__ void k_pass3(const float* __restrict__ labels, const float* __restrict__ inputs) {
    const int iv = blockIdx.x;                                  // 0..7
    const int h  = blockIdx.y * blockDim.y + threadIdx.y;       // 0..127
    const int d0 = blockIdx.z * 64;                             // 0 or 64
    const int w  = threadIdx.x;                                 // 0..127
    const float mean = g_Mean[iv];
    const float* __restrict__ S  = g_scr  + (size_t)iv * VOL;
    const float* __restrict__ Lv = labels + (size_t)iv * VOL;
    const float* __restrict__ Iv = inputs + (size_t)(iv >> 2) * VOL;
    const int hw = h * Nd + w;

    float win[9];
    #pragma unroll
    for (int k = 0; k < 8; ++k) {
        const int d = d0 - 4 + k;
        win[k] = (d >= 0) ? S[(size_t)d * SLICE + hw] : 0.f;
    }
    float numA = 0.f, denA = 0.f;
    for (int d = d0; d < d0 + 64; d += 4) {
        float nS[4], nP[4], nV[4];
        #pragma unroll
        for (int k = 0; k < 4; ++k) {         // 12 independent loads, batched
            const int dd = d + k;
            nS[k] = (dd + 4 < Nd) ? S[(size_t)(dd + 4) * SLICE + hw] : 0.f;
            nP[k] = Lv[(size_t)dd * SLICE + hw];
            nV[k] = Iv[(size_t)dd * SLICE + hw];
        }
        #pragma unroll
        for (int k = 0; k < 4; ++k) {
            win[8] = nS[k];
            float bp = 0.f;
            #pragma unroll
            for (int j = 0; j < 9; ++j) bp += Gc[j] * win[j];
            float df = nV[k] - mean;
            df *= df;
            const float wgt = __expf(-df * df);
            numA += bp * nP[k] * wgt;
            denA += bp * wgt;
            #pragma unroll
            for (int m = 0; m < 8; ++m) win[m] = win[m + 1];
        }
    }
    blockReduceAtomic(numA, denA, &g_Num[iv], &g_Den[iv]);
}

__global__ void k_final(float* __restrict__ out) {
    if (threadIdx.x == 0) {
        double loss = 0.0;
        for (int k = 0; k < 4; ++k) {
            const double nn = g_Num[k] + g_Num[k + 4];
            const double dd = g_Den[k] + g_Den[k + 4];
            loss += fabs(nn / (dd + 1e-6));
        }
        out[0] = (float)(4.0 - loss);
    }
}

extern "C" void kernel_launch(void* const* d_in, const int* in_sizes, int n_in,
                              void* d_out, int out_size) {
    const float* labels = (const float*)d_in[0];
    const float* inputs = (const float*)d_in[1];
    if (n_in >= 2 && in_sizes[0] < in_sizes[1]) {
        labels = (const float*)d_in[1];
        inputs = (const float*)d_in[0];
    }
    k_init<<<1, 32>>>();
    k_pass1<<<dim3(NVOLS, 1024), 128>>>(labels, inputs);
    k_means<<<1, 32>>>();
    k_pass2<<<dim3(Nd, NVOLS), 128>>>();
    k_pass3<<<dim3(NVOLS, 32, 2), dim3(128, 4)>>>(labels, inputs);
    k_final<<<1, 32>>>((float*)d_out);
    (void)out_size;
}